// round 8
// baseline (speedup 1.0000x reference)
#include <cuda_runtime.h>

// Fused depthwise 1D conv: 13-tap valid correlation (FD(5) ⊛ Gauss(9)).
// x: [32, 1048576] f32 -> out: [32, 1048564].
//
// SEG=4 coalesced layout (lane stride 16B -> minimal L1 wavefronts), now with
// 2 block-strided chunks per thread and all 8 LDG.128 front-batched to double
// per-thread MLP and halve per-chunk overhead. Streaming stores (__stcs):
// output is write-once, keep it out of L2.

#define T_LEN 1048576
#define L_OUT (T_LEN - 12)           // 1048564
#define CHUNKS_PER_ROW (L_OUT / 4 + 1)  // 262142 covers all (ceil)
#define THREADS 256
#define CHUNKS_PER_BLOCK (2 * THREADS)  // 512
#define BLOCKS_X 512                    // 512*512 = 262144 chunks >= 262141

__global__ __launch_bounds__(THREADS, 4)
void fused_conv13_seg4x2_kernel(const float* __restrict__ x,
                                const float* __restrict__ fd,
                                const float* __restrict__ gs,
                                float* __restrict__ out)
{
    __shared__ float c_sh[13];
    const int tid = threadIdx.x;

    // Combined 13-tap kernel: c[k] = sum_{i+j=k} fd[i]*gs[j]
    if (tid < 13) {
        float acc = 0.f;
        #pragma unroll
        for (int i = 0; i < 5; ++i) {
            int j = tid - i;
            if (j >= 0 && j < 9) acc += fd[i] * gs[j];
        }
        c_sh[tid] = acc;
    }
    __syncthreads();

    const unsigned row    = blockIdx.y;
    const unsigned chunk0 = blockIdx.x * CHUNKS_PER_BLOCK + tid;   // first chunk
    const unsigned p0     = chunk0 * 4u;                            // output idx
    const unsigned p1     = p0 + 4u * THREADS;                      // second chunk

    const float* __restrict__ xr   = x   + (size_t)row * T_LEN;
    float*       __restrict__ orow = out + (size_t)row * L_OUT;

    const bool ok0 = (p0 < L_OUT);
    const bool ok1 = (p1 < L_OUT);

    // Front-batch all 8 LDG.128 (MLP=8). Window [p, p+16) never exceeds T_LEN
    // for any valid chunk (max p = L_OUT-4 -> p+16 = T_LEN).
    float xa[16], xb[16];
    #pragma unroll
    for (int i = 0; i < 4; ++i) {
        float4 v = ok0 ? *reinterpret_cast<const float4*>(xr + p0 + i * 4)
                       : make_float4(0.f, 0.f, 0.f, 0.f);
        xa[i*4+0] = v.x; xa[i*4+1] = v.y; xa[i*4+2] = v.z; xa[i*4+3] = v.w;
    }
    #pragma unroll
    for (int i = 0; i < 4; ++i) {
        float4 v = ok1 ? *reinterpret_cast<const float4*>(xr + p1 + i * 4)
                       : make_float4(0.f, 0.f, 0.f, 0.f);
        xb[i*4+0] = v.x; xb[i*4+1] = v.y; xb[i*4+2] = v.z; xb[i*4+3] = v.w;
    }

    float cc[13];
    #pragma unroll
    for (int k = 0; k < 13; ++k) cc[k] = c_sh[k];

    // Chunk A
    if (ok0) {
        float a0 = 0.f, a1 = 0.f, a2 = 0.f, a3 = 0.f;
        #pragma unroll
        for (int k = 0; k < 13; ++k) {
            const float ck = cc[k];
            a0 = fmaf(ck, xa[k + 0], a0);
            a1 = fmaf(ck, xa[k + 1], a1);
            a2 = fmaf(ck, xa[k + 2], a2);
            a3 = fmaf(ck, xa[k + 3], a3);
        }
        float4 r; r.x = a0; r.y = a1; r.z = a2; r.w = a3;
        __stcs(reinterpret_cast<float4*>(orow + p0), r);
    }

    // Chunk B
    if (ok1) {
        float b0 = 0.f, b1 = 0.f, b2 = 0.f, b3 = 0.f;
        #pragma unroll
        for (int k = 0; k < 13; ++k) {
            const float ck = cc[k];
            b0 = fmaf(ck, xb[k + 0], b0);
            b1 = fmaf(ck, xb[k + 1], b1);
            b2 = fmaf(ck, xb[k + 2], b2);
            b3 = fmaf(ck, xb[k + 3], b3);
        }
        float4 r; r.x = b0; r.y = b1; r.z = b2; r.w = b3;
        __stcs(reinterpret_cast<float4*>(orow + p1), r);
    }
}

extern "C" void kernel_launch(void* const* d_in, const int* in_sizes, int n_in,
                              void* d_out, int out_size)
{
    const float* x  = (const float*)d_in[0];   // [8,4,1048576]
    const float* fd = (const float*)d_in[1];   // [5]
    const float* gs = (const float*)d_in[2];   // [9]
    float* out = (float*)d_out;                // [8,4,1048564]

    dim3 grid(BLOCKS_X, 32, 1);
    fused_conv13_seg4x2_kernel<<<grid, THREADS>>>(x, fd, gs, out);
}